// round 10
// baseline (speedup 1.0000x reference)
#include <cuda_runtime.h>

#define N_ROWS 2048      // 256 * 8
#define L 128
#define OUT 65
#define OUT2 (OUT * OUT) // 4225
#define THREADS 128
#define EPS 1e-6f

__global__ __launch_bounds__(THREADS) void gasf_kernel(const float* __restrict__ x,
                                                       float* __restrict__ out) {
    __shared__ float2 scss[OUT];                      // (cos, sin)
    __shared__ __align__(16) float sm_tile[OUT2 + 7]; // staged tile, shifted by pad = row%4

    const int row = blockIdx.x;
    const int tid = threadIdx.x;
    const int lane = tid & 31;
    const int wid = tid >> 5;           // 0..3
    const float POS_INF = __int_as_float(0x7f800000);

    // ---- preamble: warp 0 computes c,s (R7 pattern, warp-local) ----
    if (wid == 0) {
        float4 v = ((const float4*)(x + row * L))[lane];
        int nib = (v.x != 0.0f ? 1 : 0) | (v.y != 0.0f ? 2 : 0) |
                  (v.z != 0.0f ? 4 : 0) | (v.w != 0.0f ? 8 : 0);
        unsigned m = __ballot_sync(0xffffffffu, nib != 0);

        int first = L, last = -1;
        {
            int lf = __ffs(m) - 1;                 // junk if m==0 (guarded)
            int ll = 31 - __clz(m | 1u);
            int nf = __shfl_sync(0xffffffffu, nib, m ? lf : 0);
            int nl = __shfl_sync(0xffffffffu, nib, m ? ll : 0);
            if (m) {
                first = 4 * lf + (__ffs(nf) - 1);
                last  = 4 * ll + (31 - __clz((unsigned)nl));
            }
        }
        const int p0 = 4 * lane;
        bool val0 = (p0 + 0 >= first) && (p0 + 0 <= last);
        bool val1 = (p0 + 1 >= first) && (p0 + 1 <= last);
        bool val2 = (p0 + 2 >= first) && (p0 + 2 <= last);
        bool val3 = (p0 + 3 >= first) && (p0 + 3 <= last);
        float mn = POS_INF, mx = -POS_INF;
        if (val0) { mn = fminf(mn, v.x); mx = fmaxf(mx, v.x); }
        if (val1) { mn = fminf(mn, v.y); mx = fmaxf(mx, v.y); }
        if (val2) { mn = fminf(mn, v.z); mx = fmaxf(mx, v.z); }
        if (val3) { mn = fminf(mn, v.w); mx = fmaxf(mx, v.w); }
        #pragma unroll
        for (int off = 16; off; off >>= 1) {
            mn = fminf(mn, __shfl_xor_sync(0xffffffffu, mn, off));
            mx = fmaxf(mx, __shfl_xor_sync(0xffffffffu, mx, off));
        }
        float xmin = fminf(mn, 0.0f);          // inf (all-invalid) -> 0, clamp <= 0
        float xmax = fmaxf(mx, 0.0f);
        float inv_range = 2.0f / fmaxf(xmax - xmin, EPS);

        if (p0 < OUT) {
            float vv[4] = { v.x, v.y, v.z, v.w };
            bool vf[4] = { val0, val1, val2, val3 };
            #pragma unroll
            for (int k = 0; k < 4; ++k) {
                int p = p0 + k;
                if (p < OUT) {
                    float xn = vf[k] ? ((vv[k] - xmin) * inv_range - 1.0f) : 0.0f;
                    float c = fminf(fmaxf(xn, -1.0f + EPS), 1.0f - EPS);
                    float s = sqrtf(fmaxf(1.0f - c * c, 0.0f));
                    scss[p] = make_float2(c, s);
                }
            }
        }
    }
    __syncthreads();

    // alignment bookkeeping: global row base misaligns by 4B per row
    // 4225 % 4 == 1  =>  (row*OUT2) % 4 == row % 4 == pad, and pad+h in {0,4}
    const int pad = row & 3;                   // smem shift so smem f4 <-> global f4
    const int h = (4 - pad) & 3;               // scalar head elements
    const int t = (OUT2 - h) & 3;              // scalar tail elements
    const int nf4 = (OUT2 - h - t) >> 2;       // aligned float4 count

    // ---- build tile in smem: conflict-free R7-style body, i split over 4 warps ----
    {
        const float2 b1 = scss[lane];
        const float2 b2 = scss[lane + 32];
        const float2 b3 = scss[64];
        const float nb1y = -b1.y, nb2y = -b2.y, nb3y = -b3.y;
        float* sf = sm_tile + pad;
        #pragma unroll
        for (int i = wid; i < OUT; i += 4) {
            float2 a = scss[i];                // LDS.64 broadcast
            sf[i * OUT + lane]      = fmaf(a.x, b1.x, a.y * nb1y);   // STS stride-1
            sf[i * OUT + lane + 32] = fmaf(a.x, b2.x, a.y * nb2y);
            if (lane == 31)
                sf[i * OUT + 64]    = fmaf(a.x, b3.x, a.y * nb3y);
        }
    }
    __syncthreads();

    // ---- drain: aligned float4 stream + tiny scalar head/tail ----
    float* orow = out + (size_t)row * OUT2;
    const float4* src = (const float4*)(sm_tile + pad + h);   // 16B-aligned (pad+h in {0,4})
    float4* dst = (float4*)(orow + h);                        // 16B-aligned in gmem
    for (int q = tid; q < nf4; q += THREADS) {
        dst[q] = src[q];                       // LDS.128 + STG.128, full sectors
    }
    if (tid < h) orow[tid] = sm_tile[pad + tid];
    if (tid < t) { int e = h + 4 * nf4 + tid; orow[e] = sm_tile[pad + e]; }
}

extern "C" void kernel_launch(void* const* d_in, const int* in_sizes, int n_in,
                              void* d_out, int out_size) {
    const float* x = (const float*)d_in[0];
    float* out = (float*)d_out;
    gasf_kernel<<<N_ROWS, THREADS>>>(x, out);
}